// round 7
// baseline (speedup 1.0000x reference)
#include <cuda_runtime.h>
#include <math.h>

#define S_LEN   2048
#define EMB     1024
#define NH      16
#define HD      64
#define BATCH   2
#define M_ROWS  (BATCH * S_LEN)   // 4096

// Scratch: q,k,v in [B,h,S,d]; z in [B,S,E]
__device__ float g_q[BATCH * NH * S_LEN * HD];
__device__ float g_k[BATCH * NH * S_LEN * HD];
__device__ float g_v[BATCH * NH * S_LEN * HD];
__device__ float g_z[BATCH * S_LEN * EMB];

// Round fp32 -> tf32 (RNA). cvt.rna.tf32.f32 needs a .b32 destination.
__device__ __forceinline__ unsigned tf32u(float x) {
    unsigned r;
    asm("cvt.rna.tf32.f32 %0, %1;" : "=r"(r) : "f"(x));
    return r;
}
__device__ __forceinline__ float tf32f(float x) {
    return __uint_as_float(tf32u(x));
}

// D += A(16x8) * B(8x8), tf32 inputs, fp32 accumulate.
__device__ __forceinline__ void mma8(float* d, const unsigned* a, const unsigned* b) {
    asm volatile(
        "mma.sync.aligned.m16n8k8.row.col.f32.tf32.tf32.f32 "
        "{%0,%1,%2,%3}, {%4,%5,%6,%7}, {%8,%9}, {%0,%1,%2,%3};\n"
        : "+f"(d[0]), "+f"(d[1]), "+f"(d[2]), "+f"(d[3])
        : "r"(a[0]), "r"(a[1]), "r"(a[2]), "r"(a[3]), "r"(b[0]), "r"(b[1]));
}

// ---------------------------------------------------------------------------
// tf32 tensor-core GEMM, double-buffered, 4 warps, warp tile 64x64.
// C = A[M,K] @ B[K,N] + bias.  MODE 0: row-major; MODE 1: scatter [B,h,S,d].
// Block 128x128, BK=16, 128 threads.
// ---------------------------------------------------------------------------
template <int MODE>
__global__ __launch_bounds__(128)
void gemm_tc(const float* __restrict__ A, const float* __restrict__ B,
             const float* __restrict__ bias, float* __restrict__ C,
             int M, int N, int K)
{
    __shared__ float As[2][16][132];   // [k][m], padded
    __shared__ float Bs[2][16][132];   // [k][n], padded

    const int tid  = threadIdx.x;
    const int warp = tid >> 5, lane = tid & 31;
    const int g = lane >> 2, tg = lane & 3;
    const int wm = (warp >> 1) * 64;     // 2 warps in m
    const int wn = (warp & 1) * 64;      // 2 warps in n
    const int m0 = blockIdx.y * 128, n0 = blockIdx.x * 128;

    float acc[4][8][4];
#pragma unroll
    for (int mt = 0; mt < 4; mt++)
#pragma unroll
        for (int nt = 0; nt < 8; nt++)
#pragma unroll
            for (int c = 0; c < 4; c++) acc[mt][nt][c] = 0.f;

    // A: thread loads one row (tid), 16 k (4 float4). B: 4 float4 slots.
    auto stageA = [&](int buf, const float4* a4) {
#pragma unroll
        for (int j = 0; j < 4; j++) {
            const float* e = (const float*)&a4[j];
#pragma unroll
            for (int c = 0; c < 4; c++)
                As[buf][j * 4 + c][tid] = tf32f(e[c]);
        }
    };
    auto stageB = [&](int buf, const float4* b4) {
#pragma unroll
        for (int i = 0; i < 4; i++) {
            const int f = i * 128 + tid;
            const int r = f >> 5, c = (f & 31) * 4;
            Bs[buf][r][c + 0] = tf32f(b4[i].x);
            Bs[buf][r][c + 1] = tf32f(b4[i].y);
            Bs[buf][r][c + 2] = tf32f(b4[i].z);
            Bs[buf][r][c + 3] = tf32f(b4[i].w);
        }
    };

    // Prologue: tile 0 -> buffer 0
    {
        float4 a4[4], b4[4];
#pragma unroll
        for (int j = 0; j < 4; j++)
            a4[j] = *(const float4*)(A + (size_t)(m0 + tid) * K + j * 4);
#pragma unroll
        for (int i = 0; i < 4; i++) {
            const int f = i * 128 + tid;
            b4[i] = *(const float4*)(B + (size_t)(f >> 5) * N + n0 + (f & 31) * 4);
        }
        stageA(0, a4);
        stageB(0, b4);
    }
    __syncthreads();

    for (int k0 = 0; k0 < K; k0 += 16) {
        const int buf = (k0 >> 4) & 1;
        const bool hasNext = (k0 + 16) < K;

        float4 a4[4], b4[4];
        if (hasNext) {
            const int kn = k0 + 16;
#pragma unroll
            for (int j = 0; j < 4; j++)
                a4[j] = *(const float4*)(A + (size_t)(m0 + tid) * K + kn + j * 4);
#pragma unroll
            for (int i = 0; i < 4; i++) {
                const int f = i * 128 + tid;
                b4[i] = *(const float4*)(B + (size_t)(kn + (f >> 5)) * N + n0 + (f & 31) * 4);
            }
        }

#pragma unroll
        for (int kk = 0; kk < 16; kk += 8) {
            unsigned af[4][4];
#pragma unroll
            for (int mt = 0; mt < 4; mt++) {
                const int mb = wm + mt * 16;
                af[mt][0] = __float_as_uint(As[buf][kk + tg    ][mb + g    ]);
                af[mt][1] = __float_as_uint(As[buf][kk + tg    ][mb + g + 8]);
                af[mt][2] = __float_as_uint(As[buf][kk + tg + 4][mb + g    ]);
                af[mt][3] = __float_as_uint(As[buf][kk + tg + 4][mb + g + 8]);
            }
#pragma unroll
            for (int nt = 0; nt < 8; nt++) {
                unsigned bf[2];
                bf[0] = __float_as_uint(Bs[buf][kk + tg    ][wn + nt * 8 + g]);
                bf[1] = __float_as_uint(Bs[buf][kk + tg + 4][wn + nt * 8 + g]);
#pragma unroll
                for (int mt = 0; mt < 4; mt++)
                    mma8(acc[mt][nt], af[mt], bf);
            }
        }

        if (hasNext) {
            const int nb = buf ^ 1;
            stageA(nb, a4);
            stageB(nb, b4);
            __syncthreads();
        }
    }

    // Epilogue
#pragma unroll
    for (int mt = 0; mt < 4; mt++)
#pragma unroll
        for (int nt = 0; nt < 8; nt++)
#pragma unroll
            for (int c = 0; c < 4; c++) {
                const int m = m0 + wm + mt * 16 + g + ((c >= 2) ? 8 : 0);
                const int n = n0 + wn + nt * 8 + 2 * tg + (c & 1);
                const float v = acc[mt][nt][c] + bias[n];
                if (MODE == 0) {
                    C[(size_t)m * N + n] = v;
                } else {
                    const int b    = m >> 11;
                    const int s    = m & 2047;
                    const int head = n >> 6;
                    const int dd   = n & 63;
                    C[((((size_t)b * NH + head) * S_LEN) + s) * HD + dd] = v;
                }
            }
}

// ---------------------------------------------------------------------------
// Flash attention, tf32 tensor cores. 128 q rows per block, 4 warps (32 each:
// two m16 tiles per warp -> every smem B-fragment load feeds 2 mma).
// KV tiles of 64 via smem. P stays in registers (intra-quad shuffles).
// ---------------------------------------------------------------------------
__global__ __launch_bounds__(128)
void attn_tc(const float* __restrict__ Q, const float* __restrict__ Kp,
             const float* __restrict__ Vp, float* __restrict__ Z)
{
    __shared__ float Ks[64][68];
    __shared__ float Vs[64][68];

    const int tid  = threadIdx.x;
    const int warp = tid >> 5, lane = tid & 31;
    const int g = lane >> 2, tg = lane & 3;
    const int bh   = blockIdx.y;
    const int b    = bh >> 4, head = bh & 15;
    const int q0   = blockIdx.x * 128;
    const int rb   = warp * 32;          // warp's 32-row base within block

    // Q fragments for both m-tiles, pre-scaled by 0.125, tf32-rounded.
    unsigned qf[2][8][4];
#pragma unroll
    for (int mt = 0; mt < 2; mt++) {
        const float* qlo = Q + ((size_t)bh * S_LEN + q0 + rb + mt * 16 + g) * HD;
        const float* qhi = qlo + 8 * HD;
#pragma unroll
        for (int kt = 0; kt < 8; kt++) {
            qf[mt][kt][0] = tf32u(0.125f * qlo[kt * 8 + tg]);
            qf[mt][kt][1] = tf32u(0.125f * qhi[kt * 8 + tg]);
            qf[mt][kt][2] = tf32u(0.125f * qlo[kt * 8 + tg + 4]);
            qf[mt][kt][3] = tf32u(0.125f * qhi[kt * 8 + tg + 4]);
        }
    }

    float oacc[2][8][4];
#pragma unroll
    for (int mt = 0; mt < 2; mt++)
#pragma unroll
        for (int nt = 0; nt < 8; nt++)
#pragma unroll
            for (int c = 0; c < 4; c++) oacc[mt][nt][c] = 0.f;
    float mS[2][2], lS[2][2];
#pragma unroll
    for (int mt = 0; mt < 2; mt++) { mS[mt][0] = mS[mt][1] = -1e30f; lS[mt][0] = lS[mt][1] = 0.f; }

    const float* Kb = Kp + (size_t)bh * S_LEN * HD;
    const float* Vb = Vp + (size_t)bh * S_LEN * HD;

    const unsigned FULL = 0xffffffffu;
    const int src_a = (lane & ~3) | (tg >> 1);
    const int src_b = src_a + 2;
    const bool hi_slot = (tg & 1) != 0;

    for (int kv0 = 0; kv0 < S_LEN; kv0 += 64) {
        __syncthreads();
#pragma unroll
        for (int i = 0; i < 8; i++) {
            const int f = i * 128 + tid;
            const int r = f >> 4, c = (f & 15) * 4;
            const float4 k4 = *(const float4*)(Kb + (size_t)(kv0 + r) * HD + c);
            const float4 v4 = *(const float4*)(Vb + (size_t)(kv0 + r) * HD + c);
            float4 kc, vc;
            kc.x = tf32f(k4.x); kc.y = tf32f(k4.y); kc.z = tf32f(k4.z); kc.w = tf32f(k4.w);
            vc.x = tf32f(v4.x); vc.y = tf32f(v4.y); vc.z = tf32f(v4.z); vc.w = tf32f(v4.w);
            *(float4*)&Ks[r][c] = kc;
            *(float4*)&Vs[r][c] = vc;
        }
        __syncthreads();

        // S = Q @ K^T — each bf feeds both m-tiles
        float sacc[2][8][4];
#pragma unroll
        for (int mt = 0; mt < 2; mt++)
#pragma unroll
            for (int nt = 0; nt < 8; nt++)
#pragma unroll
                for (int c = 0; c < 4; c++) sacc[mt][nt][c] = 0.f;
#pragma unroll
        for (int kt = 0; kt < 8; kt++) {
#pragma unroll
            for (int nt = 0; nt < 8; nt++) {
                unsigned bf[2];
                bf[0] = __float_as_uint(Ks[nt * 8 + g][kt * 8 + tg]);
                bf[1] = __float_as_uint(Ks[nt * 8 + g][kt * 8 + tg + 4]);
                mma8(sacc[0][nt], qf[0][kt], bf);
                mma8(sacc[1][nt], qf[1][kt], bf);
            }
        }

        // Online softmax per m-tile
#pragma unroll
        for (int mt = 0; mt < 2; mt++) {
            float rmax_lo = -1e30f, rmax_hi = -1e30f;
#pragma unroll
            for (int nt = 0; nt < 8; nt++) {
                rmax_lo = fmaxf(rmax_lo, fmaxf(sacc[mt][nt][0], sacc[mt][nt][1]));
                rmax_hi = fmaxf(rmax_hi, fmaxf(sacc[mt][nt][2], sacc[mt][nt][3]));
            }
            rmax_lo = fmaxf(rmax_lo, __shfl_xor_sync(FULL, rmax_lo, 1));
            rmax_lo = fmaxf(rmax_lo, __shfl_xor_sync(FULL, rmax_lo, 2));
            rmax_hi = fmaxf(rmax_hi, __shfl_xor_sync(FULL, rmax_hi, 1));
            rmax_hi = fmaxf(rmax_hi, __shfl_xor_sync(FULL, rmax_hi, 2));

            const float mn_lo = fmaxf(mS[mt][0], rmax_lo);
            const float mn_hi = fmaxf(mS[mt][1], rmax_hi);
            const float corr_lo = __expf(mS[mt][0] - mn_lo);
            const float corr_hi = __expf(mS[mt][1] - mn_hi);

            float rs_lo = 0.f, rs_hi = 0.f;
#pragma unroll
            for (int nt = 0; nt < 8; nt++) {
                sacc[mt][nt][0] = __expf(sacc[mt][nt][0] - mn_lo);
                sacc[mt][nt][1] = __expf(sacc[mt][nt][1] - mn_lo);
                sacc[mt][nt][2] = __expf(sacc[mt][nt][2] - mn_hi);
                sacc[mt][nt][3] = __expf(sacc[mt][nt][3] - mn_hi);
                rs_lo += sacc[mt][nt][0] + sacc[mt][nt][1];
                rs_hi += sacc[mt][nt][2] + sacc[mt][nt][3];
            }
            rs_lo += __shfl_xor_sync(FULL, rs_lo, 1);
            rs_lo += __shfl_xor_sync(FULL, rs_lo, 2);
            rs_hi += __shfl_xor_sync(FULL, rs_hi, 1);
            rs_hi += __shfl_xor_sync(FULL, rs_hi, 2);

            lS[mt][0] = lS[mt][0] * corr_lo + rs_lo;
            lS[mt][1] = lS[mt][1] * corr_hi + rs_hi;
#pragma unroll
            for (int nt = 0; nt < 8; nt++) {
                oacc[mt][nt][0] *= corr_lo; oacc[mt][nt][1] *= corr_lo;
                oacc[mt][nt][2] *= corr_hi; oacc[mt][nt][3] *= corr_hi;
            }
            mS[mt][0] = mn_lo; mS[mt][1] = mn_hi;
        }

        // O += P @ V ; per kt permute both m-tiles' P, each bf feeds 2 mma
#pragma unroll
        for (int kt = 0; kt < 8; kt++) {
            unsigned pf[2][4];
#pragma unroll
            for (int mt = 0; mt < 2; mt++) {
                const float v0 = __shfl_sync(FULL, sacc[mt][kt][0], src_a);
                const float v1 = __shfl_sync(FULL, sacc[mt][kt][1], src_a);
                const float v2 = __shfl_sync(FULL, sacc[mt][kt][2], src_a);
                const float v3 = __shfl_sync(FULL, sacc[mt][kt][3], src_a);
                const float w0 = __shfl_sync(FULL, sacc[mt][kt][0], src_b);
                const float w1 = __shfl_sync(FULL, sacc[mt][kt][1], src_b);
                const float w2 = __shfl_sync(FULL, sacc[mt][kt][2], src_b);
                const float w3 = __shfl_sync(FULL, sacc[mt][kt][3], src_b);
                pf[mt][0] = tf32u(hi_slot ? v1 : v0);
                pf[mt][1] = tf32u(hi_slot ? v3 : v2);
                pf[mt][2] = tf32u(hi_slot ? w1 : w0);
                pf[mt][3] = tf32u(hi_slot ? w3 : w2);
            }
#pragma unroll
            for (int nt = 0; nt < 8; nt++) {
                unsigned bf[2];
                bf[0] = __float_as_uint(Vs[kt * 8 + tg    ][nt * 8 + g]);
                bf[1] = __float_as_uint(Vs[kt * 8 + tg + 4][nt * 8 + g]);
                mma8(oacc[0][nt], pf[0], bf);
                mma8(oacc[1][nt], pf[1], bf);
            }
        }
    }

#pragma unroll
    for (int mt = 0; mt < 2; mt++) {
        const float inv_lo = 1.f / lS[mt][0];
        const float inv_hi = 1.f / lS[mt][1];
        float* zlo = Z + ((size_t)(b * S_LEN + q0 + rb + mt * 16 + g)) * EMB + head * HD;
        float* zhi = zlo + (size_t)8 * EMB;
#pragma unroll
        for (int nt = 0; nt < 8; nt++) {
            zlo[nt * 8 + 2 * tg    ] = oacc[mt][nt][0] * inv_lo;
            zlo[nt * 8 + 2 * tg + 1] = oacc[mt][nt][1] * inv_lo;
            zhi[nt * 8 + 2 * tg    ] = oacc[mt][nt][2] * inv_hi;
            zhi[nt * 8 + 2 * tg + 1] = oacc[mt][nt][3] * inv_hi;
        }
    }
}

// ---------------------------------------------------------------------------
extern "C" void kernel_launch(void* const* d_in, const int* in_sizes, int n_in,
                              void* d_out, int out_size)
{
    const float* query = (const float*)d_in[0];
    const float* key_  = (const float*)d_in[1];
    const float* value = (const float*)d_in[2];
    const float* Wq = (const float*)d_in[3];
    const float* bq = (const float*)d_in[4];
    const float* Wk = (const float*)d_in[5];
    const float* bk = (const float*)d_in[6];
    const float* Wv = (const float*)d_in[7];
    const float* bv = (const float*)d_in[8];
    const float* Wo = (const float*)d_in[9];
    const float* bo = (const float*)d_in[10];
    float* out = (float*)d_out;

    float *q, *k, *v, *z;
    cudaGetSymbolAddress((void**)&q, g_q);
    cudaGetSymbolAddress((void**)&k, g_k);
    cudaGetSymbolAddress((void**)&v, g_v);
    cudaGetSymbolAddress((void**)&z, g_z);

    const dim3 gemmGrid(EMB / 128, M_ROWS / 128);   // (8, 32)
    const dim3 attnGrid(S_LEN / 128, BATCH * NH);   // (16, 32)

    gemm_tc<1><<<gemmGrid, 128>>>(query, Wq, bq, q, M_ROWS, EMB, EMB);
    gemm_tc<1><<<gemmGrid, 128>>>(key_,  Wk, bk, k, M_ROWS, EMB, EMB);
    gemm_tc<1><<<gemmGrid, 128>>>(value, Wv, bv, v, M_ROWS, EMB, EMB);
    attn_tc<<<attnGrid, 128>>>(q, k, v, z);
    gemm_tc<0><<<gemmGrid, 128>>>(z, Wo, bo, out, M_ROWS, EMB, EMB);
}